// round 6
// baseline (speedup 1.0000x reference)
#include <cuda_runtime.h>
#include <cuda_bf16.h>

#define BATCH 128
#define DIM 128
#define K1 4097            // K + 1
#define OUTPUT_SIZE 200000
#define SCORE_STRIDE (BATCH * K1)          // 524416 per score tensor
#define BANK_ELEMS (OUTPUT_SIZE * DIM)     // 25,600,000
#define MOMENTUM 0.5f

// ---------------------------------------------------------------------------
// Score kernel: one warp per (b, k). Each lane owns 4 consecutive floats of
// the 128-dim row (float4), so a row read is one coalesced 512B transaction.
// 6 dot products per (b,k):
//   w_l  : ab -> out0, ori -> out2
//   w_ab : l  -> out1, ori -> out5
//   w_ori: l  -> out3, ab  -> out4
// Stack order: [ab2l, l2ab, ori2l, l2ori, ab2ori, ori2ab]
// ---------------------------------------------------------------------------
__global__ __launch_bounds__(256) void score_kernel(
    const float* __restrict__ l,
    const float* __restrict__ ab,
    const float* __restrict__ ori,
    const int* __restrict__ idx,
    const float* __restrict__ ml,
    const float* __restrict__ mab,
    const float* __restrict__ mori,
    float* __restrict__ outs)
{
    const int b    = blockIdx.y;
    const int tid  = threadIdx.x;
    const int warp = tid >> 5;
    const int lane = tid & 31;

    __shared__ float4 sl[32], sab[32], sori[32];
    if (tid < 32) {
        sl[tid] = reinterpret_cast<const float4*>(l + (size_t)b * DIM)[tid];
    } else if (tid < 64) {
        sab[tid - 32] = reinterpret_cast<const float4*>(ab + (size_t)b * DIM)[tid - 32];
    } else if (tid < 96) {
        sori[tid - 64] = reinterpret_cast<const float4*>(ori + (size_t)b * DIM)[tid - 64];
    }
    __syncthreads();

    const int k = blockIdx.x * 8 + warp;
    if (k >= K1) return;

    const int row = __ldg(&idx[(size_t)b * K1 + k]);   // uniform across warp

    const float4 fl = sl[lane];
    const float4 fa = sab[lane];
    const float4 fo = sori[lane];

    const float4 vl = reinterpret_cast<const float4*>(ml  + (size_t)row * DIM)[lane];
    const float4 va = reinterpret_cast<const float4*>(mab + (size_t)row * DIM)[lane];
    const float4 vo = reinterpret_cast<const float4*>(mori + (size_t)row * DIM)[lane];

    float s0 = vl.x * fa.x + vl.y * fa.y + vl.z * fa.z + vl.w * fa.w;  // ab2l
    float s2 = vl.x * fo.x + vl.y * fo.y + vl.z * fo.z + vl.w * fo.w;  // ori2l
    float s1 = va.x * fl.x + va.y * fl.y + va.z * fl.z + va.w * fl.w;  // l2ab
    float s5 = va.x * fo.x + va.y * fo.y + va.z * fo.z + va.w * fo.w;  // ori2ab
    float s3 = vo.x * fl.x + vo.y * fl.y + vo.z * fl.z + vo.w * fl.w;  // l2ori
    float s4 = vo.x * fa.x + vo.y * fa.y + vo.z * fa.z + vo.w * fa.w;  // ab2ori

    #pragma unroll
    for (int off = 16; off > 0; off >>= 1) {
        s0 += __shfl_xor_sync(0xffffffffu, s0, off);
        s1 += __shfl_xor_sync(0xffffffffu, s1, off);
        s2 += __shfl_xor_sync(0xffffffffu, s2, off);
        s3 += __shfl_xor_sync(0xffffffffu, s3, off);
        s4 += __shfl_xor_sync(0xffffffffu, s4, off);
        s5 += __shfl_xor_sync(0xffffffffu, s5, off);
    }

    if (lane == 0) {
        const size_t base = (size_t)b * K1 + k;
        outs[0 * (size_t)SCORE_STRIDE + base] = s0;
        outs[1 * (size_t)SCORE_STRIDE + base] = s1;
        outs[2 * (size_t)SCORE_STRIDE + base] = s2;
        outs[3 * (size_t)SCORE_STRIDE + base] = s3;
        outs[4 * (size_t)SCORE_STRIDE + base] = s4;
        outs[5 * (size_t)SCORE_STRIDE + base] = s5;
    }
}

// ---------------------------------------------------------------------------
// Momentum update of 128 rows per bank. One block per batch element b,
// 128 threads = one element each. Reads OLD bank values from the (const)
// input, writes into the already-copied output bank. Duplicate y: last b wins
// (skip if a later b has the same target row) — matches scatter-set.
// ---------------------------------------------------------------------------
__device__ __forceinline__ void update_one(
    const float* __restrict__ mem, const float* __restrict__ feat,
    float* __restrict__ out, int row, int b, int d, float* red, int slot)
{
    const float pos = mem[(size_t)row * DIM + d] * MOMENTUM
                    + feat[(size_t)b * DIM + d] * (1.0f - MOMENTUM);
    float v = pos * pos;
    #pragma unroll
    for (int off = 16; off > 0; off >>= 1)
        v += __shfl_xor_sync(0xffffffffu, v, off);
    if ((d & 31) == 0) red[slot * 4 + (d >> 5)] = v;
    __syncthreads();
    const float sum = red[slot * 4 + 0] + red[slot * 4 + 1]
                    + red[slot * 4 + 2] + red[slot * 4 + 3];
    out[(size_t)row * DIM + d] = pos / sqrtf(sum);
}

__global__ __launch_bounds__(128) void update_kernel(
    const float* __restrict__ l,
    const float* __restrict__ ab,
    const float* __restrict__ ori,
    const int* __restrict__ y,
    const float* __restrict__ ml,
    const float* __restrict__ mab,
    const float* __restrict__ mori,
    float* __restrict__ nl,
    float* __restrict__ nab,
    float* __restrict__ nori)
{
    const int b = blockIdx.x;
    const int row = y[b];
    // last-occurrence-wins: skip if a later batch element targets the same row
    for (int j = b + 1; j < BATCH; ++j)
        if (y[j] == row) return;

    const int d = threadIdx.x;
    __shared__ float red[12];

    update_one(ml,  l,   nl,   row, b, d, red, 0);
    update_one(mab, ab,  nab,  row, b, d, red, 1);
    update_one(mori, ori, nori, row, b, d, red, 2);
}

// ---------------------------------------------------------------------------
extern "C" void kernel_launch(void* const* d_in, const int* in_sizes, int n_in,
                              void* d_out, int out_size)
{
    const float* l    = (const float*)d_in[0];
    const float* ab   = (const float*)d_in[1];
    const float* ori  = (const float*)d_in[2];
    const int*   y    = (const int*)d_in[3];
    const int*   idx  = (const int*)d_in[4];
    const float* ml   = (const float*)d_in[5];
    const float* mab  = (const float*)d_in[6];
    const float* mori = (const float*)d_in[7];

    float* outs = (float*)d_out;
    float* nl   = outs + (size_t)6 * SCORE_STRIDE;
    float* nab  = nl  + (size_t)BANK_ELEMS;
    float* nori = nab + (size_t)BANK_ELEMS;

    const size_t bank_bytes = (size_t)BANK_ELEMS * sizeof(float);

    // Full-bank copies (D2D memcpy nodes are graph-capturable)
    cudaMemcpyAsync(nl,   ml,   bank_bytes, cudaMemcpyDeviceToDevice, 0);
    cudaMemcpyAsync(nab,  mab,  bank_bytes, cudaMemcpyDeviceToDevice, 0);
    cudaMemcpyAsync(nori, mori, bank_bytes, cudaMemcpyDeviceToDevice, 0);

    // Scores: grid (ceil(4097/8), 128), 8 warps/block = 8 k-values per block
    dim3 sgrid((K1 + 7) / 8, BATCH);
    score_kernel<<<sgrid, 256>>>(l, ab, ori, idx, ml, mab, mori, outs);

    // Momentum scatter-update of the 128 touched rows per bank
    update_kernel<<<BATCH, 128>>>(l, ab, ori, y, ml, mab, mori, nl, nab, nori);
}

// round 7
// speedup vs baseline: 1.1299x; 1.1299x over previous
#include <cuda_runtime.h>
#include <cuda_bf16.h>

#define BATCH 128
#define DIM 128
#define K1 4097                              // K + 1
#define OUTPUT_SIZE 200000
#define SCORE_STRIDE (BATCH * K1)            // 524416 per score tensor
#define BANK_ELEMS (OUTPUT_SIZE * DIM)       // 25,600,000 floats per bank
#define MOMENTUM 0.5f

#define KTILES 513                            // ceil(4097 / 8)
#define SCORE_BLOCKS (BATCH * KTILES)         // 65664
#define GROUPS (SCORE_BLOCKS / 8)             // 8208 (8 score + 1 copy per group)
#define TOTAL_BLOCKS (GROUPS * 9)             // 73872
#define COPY_THREADS ((size_t)GROUPS * 256)   // 2,101,248
#define BANK_VEC (BANK_ELEMS / 4)             // 6,400,000 float4 per bank

// ---------------------------------------------------------------------------
// Fused kernel: every 9th block streams the bank copies (no-reuse data, so
// ld.cs/st.cs to keep it out of the score gathers' L2 working set); the other
// 8/9 blocks compute scores (one warp per (b,k), float4 lanes -> one fully
// coalesced 512B row read per bank). Copy and score overlap on the memory
// system inside a single launch.
// Stack order: [ab2l, l2ab, ori2l, l2ori, ab2ori, ori2ab]
// ---------------------------------------------------------------------------
__global__ __launch_bounds__(256) void fused_kernel(
    const float* __restrict__ l,
    const float* __restrict__ ab,
    const float* __restrict__ ori,
    const int* __restrict__ idx,
    const float* __restrict__ ml,
    const float* __restrict__ mab,
    const float* __restrict__ mori,
    float* __restrict__ outs,
    float* __restrict__ nl,
    float* __restrict__ nab,
    float* __restrict__ nori)
{
    const int bid = blockIdx.x;
    const int g   = bid / 9;
    const int r   = bid - g * 9;
    const int tid = threadIdx.x;

    if (r == 8) {
        // ------------------- copy block (1 of GROUPS) -------------------
        const size_t start  = (size_t)g * 256 + tid;
        const size_t stride = COPY_THREADS;

        const float4* s0 = (const float4*)ml;
        const float4* s1 = (const float4*)mab;
        const float4* s2 = (const float4*)mori;
        float4* d0 = (float4*)nl;
        float4* d1 = (float4*)nab;
        float4* d2 = (float4*)nori;

        for (size_t i = start; i < (size_t)BANK_VEC; i += stride)
            __stcs(&d0[i], __ldcs(&s0[i]));
        for (size_t i = start; i < (size_t)BANK_VEC; i += stride)
            __stcs(&d1[i], __ldcs(&s1[i]));
        for (size_t i = start; i < (size_t)BANK_VEC; i += stride)
            __stcs(&d2[i], __ldcs(&s2[i]));
        return;
    }

    // ---------------------- score block (8 of 9) ----------------------
    const int score_id = g * 8 + r;           // 0 .. SCORE_BLOCKS-1
    const int b    = score_id / KTILES;
    const int tile = score_id - b * KTILES;
    const int warp = tid >> 5;
    const int lane = tid & 31;

    __shared__ float4 sl[32], sab[32], sori[32];
    if (tid < 32) {
        sl[tid] = reinterpret_cast<const float4*>(l + (size_t)b * DIM)[tid];
    } else if (tid < 64) {
        sab[tid - 32] = reinterpret_cast<const float4*>(ab + (size_t)b * DIM)[tid - 32];
    } else if (tid < 96) {
        sori[tid - 64] = reinterpret_cast<const float4*>(ori + (size_t)b * DIM)[tid - 64];
    }
    __syncthreads();

    const int k = tile * 8 + warp;
    if (k >= K1) return;

    const int row = __ldg(&idx[(size_t)b * K1 + k]);   // uniform across warp

    const float4 fl = sl[lane];
    const float4 fa = sab[lane];
    const float4 fo = sori[lane];

    const float4 vl = __ldg(&reinterpret_cast<const float4*>(ml   + (size_t)row * DIM)[lane]);
    const float4 va = __ldg(&reinterpret_cast<const float4*>(mab  + (size_t)row * DIM)[lane]);
    const float4 vo = __ldg(&reinterpret_cast<const float4*>(mori + (size_t)row * DIM)[lane]);

    float s0 = vl.x * fa.x + vl.y * fa.y + vl.z * fa.z + vl.w * fa.w;  // ab2l
    float s2 = vl.x * fo.x + vl.y * fo.y + vl.z * fo.z + vl.w * fo.w;  // ori2l
    float s1 = va.x * fl.x + va.y * fl.y + va.z * fl.z + va.w * fl.w;  // l2ab
    float s5 = va.x * fo.x + va.y * fo.y + va.z * fo.z + va.w * fo.w;  // ori2ab
    float s3 = vo.x * fl.x + vo.y * fl.y + vo.z * fl.z + vo.w * fl.w;  // l2ori
    float s4 = vo.x * fa.x + vo.y * fa.y + vo.z * fa.z + vo.w * fa.w;  // ab2ori

    #pragma unroll
    for (int off = 16; off > 0; off >>= 1) {
        s0 += __shfl_xor_sync(0xffffffffu, s0, off);
        s1 += __shfl_xor_sync(0xffffffffu, s1, off);
        s2 += __shfl_xor_sync(0xffffffffu, s2, off);
        s3 += __shfl_xor_sync(0xffffffffu, s3, off);
        s4 += __shfl_xor_sync(0xffffffffu, s4, off);
        s5 += __shfl_xor_sync(0xffffffffu, s5, off);
    }

    if (lane == 0) {
        const size_t base = (size_t)b * K1 + k;
        outs[0 * (size_t)SCORE_STRIDE + base] = s0;
        outs[1 * (size_t)SCORE_STRIDE + base] = s1;
        outs[2 * (size_t)SCORE_STRIDE + base] = s2;
        outs[3 * (size_t)SCORE_STRIDE + base] = s3;
        outs[4 * (size_t)SCORE_STRIDE + base] = s4;
        outs[5 * (size_t)SCORE_STRIDE + base] = s5;
    }
}

// ---------------------------------------------------------------------------
// Momentum update of the 128 touched rows per bank. One block per batch
// element, 128 threads. y is staged in shared (was: up to 127 serial global
// loads per block). All 3 banks reduced in a single shuffle round + one sync.
// Duplicate y: last occurrence wins (scatter-set semantics).
// ---------------------------------------------------------------------------
__global__ __launch_bounds__(128) void update_kernel(
    const float* __restrict__ l,
    const float* __restrict__ ab,
    const float* __restrict__ ori,
    const int* __restrict__ y,
    const float* __restrict__ ml,
    const float* __restrict__ mab,
    const float* __restrict__ mori,
    float* __restrict__ nl,
    float* __restrict__ nab,
    float* __restrict__ nori)
{
    __shared__ int sy[BATCH];
    __shared__ float red[12];

    const int b = blockIdx.x;
    const int d = threadIdx.x;

    sy[d] = y[d];
    __syncthreads();

    const int row = sy[b];
    for (int j = b + 1; j < BATCH; ++j)
        if (sy[j] == row) return;            // block-uniform exit

    const size_t mo = (size_t)row * DIM + d;
    const size_t fo = (size_t)b * DIM + d;

    const float pl = ml[mo]   * MOMENTUM + l[fo]   * (1.0f - MOMENTUM);
    const float pa = mab[mo]  * MOMENTUM + ab[fo]  * (1.0f - MOMENTUM);
    const float po = mori[mo] * MOMENTUM + ori[fo] * (1.0f - MOMENTUM);

    float vl = pl * pl, va = pa * pa, vo = po * po;
    #pragma unroll
    for (int off = 16; off > 0; off >>= 1) {
        vl += __shfl_xor_sync(0xffffffffu, vl, off);
        va += __shfl_xor_sync(0xffffffffu, va, off);
        vo += __shfl_xor_sync(0xffffffffu, vo, off);
    }
    const int w = d >> 5;
    if ((d & 31) == 0) { red[w] = vl; red[4 + w] = va; red[8 + w] = vo; }
    __syncthreads();

    const float suml = red[0] + red[1] + red[2]  + red[3];
    const float suma = red[4] + red[5] + red[6]  + red[7];
    const float sumo = red[8] + red[9] + red[10] + red[11];

    nl[mo]   = pl / sqrtf(suml);
    nab[mo]  = pa / sqrtf(suma);
    nori[mo] = po / sqrtf(sumo);
}

// ---------------------------------------------------------------------------
extern "C" void kernel_launch(void* const* d_in, const int* in_sizes, int n_in,
                              void* d_out, int out_size)
{
    const float* l    = (const float*)d_in[0];
    const float* ab   = (const float*)d_in[1];
    const float* ori  = (const float*)d_in[2];
    const int*   y    = (const int*)d_in[3];
    const int*   idx  = (const int*)d_in[4];
    const float* ml   = (const float*)d_in[5];
    const float* mab  = (const float*)d_in[6];
    const float* mori = (const float*)d_in[7];

    float* outs = (float*)d_out;
    float* nl   = outs + (size_t)6 * SCORE_STRIDE;
    float* nab  = nl  + (size_t)BANK_ELEMS;
    float* nori = nab + (size_t)BANK_ELEMS;

    fused_kernel<<<TOTAL_BLOCKS, 256>>>(l, ab, ori, idx, ml, mab, mori,
                                        outs, nl, nab, nori);
    update_kernel<<<BATCH, 128>>>(l, ab, ori, y, ml, mab, mori, nl, nab, nori);
}

// round 8
// speedup vs baseline: 1.5259x; 1.3505x over previous
#include <cuda_runtime.h>
#include <cuda_bf16.h>

#define BATCH 128
#define DIM 128
#define K1 4097                              // K + 1
#define OUTPUT_SIZE 200000
#define NENTRIES (BATCH * K1)                // 524416 (b,k) pairs
#define SCORE_STRIDE NENTRIES                // per score plane
#define BANK_ELEMS (OUTPUT_SIZE * DIM)       // 25,600,000 floats per bank
#define MOMENTUM 0.5f

// ---- CSR inverted index scratch (static device globals; no runtime alloc) ----
#define NSCAN (OUTPUT_SIZE + 1)              // 200001
#define SCAN_TPB 256
#define SCAN_EPT 4
#define SCAN_EPB (SCAN_TPB * SCAN_EPT)       // 1024
#define SCAN_NBLK ((NSCAN + SCAN_EPB - 1) / SCAN_EPB)  // 196

__device__ int      g_count[NSCAN];          // histogram -> exclusive offsets
__device__ int      g_cursor[OUTPUT_SIZE];   // scatter cursors (copy of offsets)
__device__ unsigned g_entries[NENTRIES];     // packed (b<<13)|k
__device__ int      g_blocksums[SCAN_NBLK];

// ---------------------------------------------------------------------------
// 1) zero the histogram
// ---------------------------------------------------------------------------
__global__ void zero_kernel() {
    int i = blockIdx.x * blockDim.x + threadIdx.x;
    if (i < NSCAN) g_count[i] = 0;
}

// ---------------------------------------------------------------------------
// 2) histogram of idx values
// ---------------------------------------------------------------------------
__global__ void hist_kernel(const int* __restrict__ idx) {
    int i = blockIdx.x * blockDim.x + threadIdx.x;
    if (i < NENTRIES) atomicAdd(&g_count[idx[i]], 1);
}

// ---------------------------------------------------------------------------
// 3) two-level exclusive scan of g_count (200001 elements)
// ---------------------------------------------------------------------------
__global__ void scan1_kernel() {
    const int b = blockIdx.x, t = threadIdx.x;
    const int base = b * SCAN_EPB + t * SCAN_EPT;
    int s = 0;
    #pragma unroll
    for (int i = 0; i < SCAN_EPT; i++) {
        int e = base + i;
        if (e < NSCAN) s += g_count[e];
    }
    __shared__ int red[8];
    #pragma unroll
    for (int off = 16; off; off >>= 1) s += __shfl_xor_sync(~0u, s, off);
    if ((t & 31) == 0) red[t >> 5] = s;
    __syncthreads();
    if (t == 0) {
        int tot = 0;
        #pragma unroll
        for (int i = 0; i < 8; i++) tot += red[i];
        g_blocksums[b] = tot;
    }
}

__global__ void scan2_kernel() {
    const int t = threadIdx.x;
    __shared__ int sm[SCAN_TPB];
    sm[t] = (t < SCAN_NBLK) ? g_blocksums[t] : 0;
    __syncthreads();
    for (int off = 1; off < SCAN_TPB; off <<= 1) {
        int add = (t >= off) ? sm[t - off] : 0;
        __syncthreads();
        sm[t] += add;
        __syncthreads();
    }
    if (t < SCAN_NBLK) g_blocksums[t] = (t == 0) ? 0 : sm[t - 1];
}

__global__ void scan3_kernel() {
    const int b = blockIdx.x, t = threadIdx.x;
    const int base = b * SCAN_EPB + t * SCAN_EPT;
    int v[SCAN_EPT];
    int tsum = 0;
    #pragma unroll
    for (int i = 0; i < SCAN_EPT; i++) {
        int e = base + i;
        v[i] = (e < NSCAN) ? g_count[e] : 0;
        tsum += v[i];
    }
    __shared__ int sm[SCAN_TPB];
    sm[t] = tsum;
    __syncthreads();
    for (int off = 1; off < SCAN_TPB; off <<= 1) {
        int add = (t >= off) ? sm[t - off] : 0;
        __syncthreads();
        sm[t] += add;
        __syncthreads();
    }
    int run = g_blocksums[b] + ((t == 0) ? 0 : sm[t - 1]);
    #pragma unroll
    for (int i = 0; i < SCAN_EPT; i++) {
        int e = base + i;
        if (e < NSCAN) {
            g_count[e] = run;
            if (e < OUTPUT_SIZE) g_cursor[e] = run;
        }
        run += v[i];
    }
}

// ---------------------------------------------------------------------------
// 4) scatter entries into CSR buckets
// ---------------------------------------------------------------------------
__global__ void scatter_kernel(const int* __restrict__ idx) {
    int i = blockIdx.x * blockDim.x + threadIdx.x;
    if (i >= NENTRIES) return;
    const int r = idx[i];
    const int pos = atomicAdd(&g_cursor[r], 1);
    const int b = i / K1;
    const int k = i - b * K1;
    g_entries[pos] = ((unsigned)b << 13) | (unsigned)k;
}

// ---------------------------------------------------------------------------
// 5) main pass: one warp per bank row. Each lane holds float4 of each of the
// 3 bank rows in registers (one streaming 512B read per bank), writes the
// copy (streaming stores), then serves every (b,k) entry referencing this
// row from registers: 3 feature loads (196KB total, L1-hot), 6 dots,
// butterfly reduce, scattered score writes.
// Stack order: [ab2l, l2ab, ori2l, l2ori, ab2ori, ori2ab]
// ---------------------------------------------------------------------------
__global__ __launch_bounds__(256) void main_kernel(
    const float* __restrict__ l,
    const float* __restrict__ ab,
    const float* __restrict__ ori,
    const float* __restrict__ ml,
    const float* __restrict__ mab,
    const float* __restrict__ mori,
    float* __restrict__ outs,
    float* __restrict__ nl,
    float* __restrict__ nab,
    float* __restrict__ nori)
{
    const int warp = threadIdx.x >> 5;
    const int lane = threadIdx.x & 31;
    const int row  = blockIdx.x * 8 + warp;          // 25000*8 = 200000 exact

    const size_t voff = (size_t)row * 32 + lane;

    const float4 vl = __ldcs((const float4*)ml   + voff);
    const float4 va = __ldcs((const float4*)mab  + voff);
    const float4 vo = __ldcs((const float4*)mori + voff);

    __stcs((float4*)nl   + voff, vl);
    __stcs((float4*)nab  + voff, va);
    __stcs((float4*)nori + voff, vo);

    const int e0 = g_count[row];
    const int e1 = g_count[row + 1];

    for (int e = e0; e < e1; e++) {
        const unsigned ent = g_entries[e];           // warp-uniform broadcast
        const int b = (int)(ent >> 13);
        const int k = (int)(ent & 8191u);

        const size_t foff = (size_t)b * 32 + lane;
        const float4 fl = __ldg((const float4*)l   + foff);
        const float4 fa = __ldg((const float4*)ab  + foff);
        const float4 fo = __ldg((const float4*)ori + foff);

        float s0 = vl.x * fa.x + vl.y * fa.y + vl.z * fa.z + vl.w * fa.w;  // ab2l
        float s2 = vl.x * fo.x + vl.y * fo.y + vl.z * fo.z + vl.w * fo.w;  // ori2l
        float s1 = va.x * fl.x + va.y * fl.y + va.z * fl.z + va.w * fl.w;  // l2ab
        float s5 = va.x * fo.x + va.y * fo.y + va.z * fo.z + va.w * fo.w;  // ori2ab
        float s3 = vo.x * fl.x + vo.y * fl.y + vo.z * fl.z + vo.w * fl.w;  // l2ori
        float s4 = vo.x * fa.x + vo.y * fa.y + vo.z * fa.z + vo.w * fa.w;  // ab2ori

        #pragma unroll
        for (int off = 16; off > 0; off >>= 1) {
            s0 += __shfl_xor_sync(0xffffffffu, s0, off);
            s1 += __shfl_xor_sync(0xffffffffu, s1, off);
            s2 += __shfl_xor_sync(0xffffffffu, s2, off);
            s3 += __shfl_xor_sync(0xffffffffu, s3, off);
            s4 += __shfl_xor_sync(0xffffffffu, s4, off);
            s5 += __shfl_xor_sync(0xffffffffu, s5, off);
        }

        if (lane == 0) {
            const size_t base = (size_t)b * K1 + k;
            outs[0 * (size_t)SCORE_STRIDE + base] = s0;
            outs[1 * (size_t)SCORE_STRIDE + base] = s1;
            outs[2 * (size_t)SCORE_STRIDE + base] = s2;
            outs[3 * (size_t)SCORE_STRIDE + base] = s3;
            outs[4 * (size_t)SCORE_STRIDE + base] = s4;
            outs[5 * (size_t)SCORE_STRIDE + base] = s5;
        }
    }
}

// ---------------------------------------------------------------------------
// 6) momentum update of the 128 touched rows (overwrites the copied rows).
// Duplicate y: last occurrence wins (scatter-set semantics).
// ---------------------------------------------------------------------------
__global__ __launch_bounds__(128) void update_kernel(
    const float* __restrict__ l,
    const float* __restrict__ ab,
    const float* __restrict__ ori,
    const int* __restrict__ y,
    const float* __restrict__ ml,
    const float* __restrict__ mab,
    const float* __restrict__ mori,
    float* __restrict__ nl,
    float* __restrict__ nab,
    float* __restrict__ nori)
{
    __shared__ int sy[BATCH];
    __shared__ float red[12];

    const int b = blockIdx.x;
    const int d = threadIdx.x;

    sy[d] = y[d];
    __syncthreads();

    const int row = sy[b];
    for (int j = b + 1; j < BATCH; ++j)
        if (sy[j] == row) return;            // block-uniform exit

    const size_t mo = (size_t)row * DIM + d;
    const size_t fo = (size_t)b * DIM + d;

    const float pl = ml[mo]   * MOMENTUM + l[fo]   * (1.0f - MOMENTUM);
    const float pa = mab[mo]  * MOMENTUM + ab[fo]  * (1.0f - MOMENTUM);
    const float po = mori[mo] * MOMENTUM + ori[fo] * (1.0f - MOMENTUM);

    float vl = pl * pl, va = pa * pa, vo = po * po;
    #pragma unroll
    for (int off = 16; off > 0; off >>= 1) {
        vl += __shfl_xor_sync(0xffffffffu, vl, off);
        va += __shfl_xor_sync(0xffffffffu, va, off);
        vo += __shfl_xor_sync(0xffffffffu, vo, off);
    }
    const int w = d >> 5;
    if ((d & 31) == 0) { red[w] = vl; red[4 + w] = va; red[8 + w] = vo; }
    __syncthreads();

    const float suml = red[0] + red[1] + red[2]  + red[3];
    const float suma = red[4] + red[5] + red[6]  + red[7];
    const float sumo = red[8] + red[9] + red[10] + red[11];

    nl[mo]   = pl / sqrtf(suml);
    nab[mo]  = pa / sqrtf(suma);
    nori[mo] = po / sqrtf(sumo);
}

// ---------------------------------------------------------------------------
extern "C" void kernel_launch(void* const* d_in, const int* in_sizes, int n_in,
                              void* d_out, int out_size)
{
    const float* l    = (const float*)d_in[0];
    const float* ab   = (const float*)d_in[1];
    const float* ori  = (const float*)d_in[2];
    const int*   y    = (const int*)d_in[3];
    const int*   idx  = (const int*)d_in[4];
    const float* ml   = (const float*)d_in[5];
    const float* mab  = (const float*)d_in[6];
    const float* mori = (const float*)d_in[7];

    float* outs = (float*)d_out;
    float* nl   = outs + (size_t)6 * SCORE_STRIDE;
    float* nab  = nl  + (size_t)BANK_ELEMS;
    float* nori = nab + (size_t)BANK_ELEMS;

    // Build CSR inverted index: row -> list of (b,k)
    zero_kernel<<<(NSCAN + 255) / 256, 256>>>();
    hist_kernel<<<(NENTRIES + 255) / 256, 256>>>(idx);
    scan1_kernel<<<SCAN_NBLK, SCAN_TPB>>>();
    scan2_kernel<<<1, SCAN_TPB>>>();
    scan3_kernel<<<SCAN_NBLK, SCAN_TPB>>>();
    scatter_kernel<<<(NENTRIES + 255) / 256, 256>>>(idx);

    // Single sweep over the banks: copy + all gathered dot products
    main_kernel<<<OUTPUT_SIZE / 8, 256>>>(l, ab, ori, ml, mab, mori,
                                          outs, nl, nab, nori);

    // Momentum scatter-update of the 128 touched rows per bank
    update_kernel<<<BATCH, 128>>>(l, ab, ori, y, ml, mab, mori, nl, nab, nori);
}